// round 15
// baseline (speedup 1.0000x reference)
#include <cuda_runtime.h>

// SCL polar decoder, neural-MLP variant. Round 14 = Round 13 + layer-2
// thread remap: each warp now covers 32 output cols (cq 0..7, 4-way row
// duplication) instead of 64, halving the W2 LDG footprint per warp from
// 256B (2 wavefronts) to 128B (1 wavefront). Same registers, same per-col
// ascending-k accumulation -> bit-identical to round 13.
//  - embH precompute; BIG TILE=64/RT=8 + prefetch both layers; SMALL RT{4,2,1}
//  - FFMA2 packed math; activations smem-resident; uniform-list elimination

#define NLIST 8
#define DE    64
#define HD    256
#define DU    16
#define NB    128
#define NT    512

typedef unsigned long long u64t;

__device__ float g_embH[2*HD];   // identical values written by every block

struct Params {
  const float *Wo1, *bo1, *Wo2, *bo2;
  const float *Wc1, *bc1, *Wc2, *bc2;
  const float *Wb1, *bb1, *Wb2, *bb2;
  const float *Wllr, *bllr, *emb;
};

// E buffer offsets inside the flat smem array (floats)
#define EO1   0        // 8*32*64 = 16384
#define EO2   16384    // 8*16*64 = 8192
#define EO3   24576    // 4096
#define EO4   28672    // 2048
#define EO5   30720    // 1024
#define EO6   31744    // 512
#define EO0   32256    // single list: 64*64 = 4096
#define YO    36352    // obs input staging: 64*4 = 256
#define EALLN 36608

#define BST   260      // Bh row stride (16B-aligned rows)

__host__ __device__ constexpr int EOlvl(int L){
  return (L==0)?EO0:(L==1)?EO1:(L==2)?EO2:(L==3)?EO3:(L==4)?EO4:(L==5)?EO5:EO6;
}
__host__ __device__ constexpr int OOFFc(int k){ int o=0; for(int i=0;i<k;i++) o += 8*(64>>i); return o; }
__host__ __device__ constexpr int SOFFc(int k){ int o=0; for(int i=0;i<k;i++) o += 4*(64>>i); return o; }

struct __align__(16) Smem {
  float EALL[EALLN];   // all E levels + y staging
  float Bh[64*BST];    // hidden tile [r][h]; small path aliases Part at row 32
  int   Uout[1016];
  int   Xout[1016];
  float Lout[1016];
  int   U1[504];
  int   X1[504];
  float L1f[504];
  int   Ord1[48];
  int   Ord2[8];
  int   Ret[8];
  float Pm[8];
  float PmNew[8];
  float Llr[8];
  float Abs[8];
  int   Hd[8];
  int   first_info;
};

struct RowOff { int e; int bit; };

// ---- packed f32x2 helpers ----
__device__ __forceinline__ u64t pack2(float x){
  u64t r;
  asm("mov.b64 %0, {%1, %1};" : "=l"(r) : "f"(x));
  return r;
}
__device__ __forceinline__ void ffma2(u64t& acc, u64t a, u64t b){
  asm("fma.rn.f32x2 %0, %1, %2, %0;" : "+l"(acc) : "l"(a), "l"(b));
}
__device__ __forceinline__ u64t fadd2(u64t a, u64t b){
  u64t r;
  asm("add.rn.f32x2 %0, %1, %2;" : "=l"(r) : "l"(a), "l"(b));
  return r;
}
__device__ __forceinline__ void unpack2(u64t v, float& lo, float& hi){
  asm("mov.b64 {%0, %1}, %2;" : "=f"(lo), "=f"(hi) : "l"(v));
}

// ================= BIG path: R >= 64, TILE=64, RT=8 =================
template<int K, bool EMB, typename RowOffF>
__device__ void run_mlp_big(Smem& sm, int R,
    const float* __restrict__ W1, const float* __restrict__ b1,
    const float* __restrict__ W2, const float* __restrict__ b2,
    int EoutOff, RowOffF rowoff)
{
  constexpr int RT    = 8;
  constexpr int TILE  = 64;

  const int tid = threadIdx.x;
  const int hq  = tid & 63;
  const int rg  = tid >> 6;        // 0..7
  // layer-2 remap: warp covers 32 cols (1-wavefront W2 loads), 4-way row dup
  const int cq8 = tid & 7;         // col quad within half
  const int rr  = (tid >> 3) & 31; // row 0..31 (second row = rr+32)
  const int ch  = tid >> 8;        // col half 0..1 (constant per warp)
  const int wi  = ch*8 + cq8;      // ulonglong2 index into a 64-col W2 row
  const ulonglong2 bb1p = ((const ulonglong2*)b1)[hq];
  const ulonglong2 bb2p = ((const ulonglong2*)b2)[wi];

  for (int r0 = 0; r0 < R; r0 += TILE) {
    // ---- layer 1: RT=8 row reuse, double-buffered weight prefetch ----
    {
      ulonglong2 acc[RT];
      int roE[RT];
      #pragma unroll
      for (int j=0;j<RT;j++){
        int r = r0 + rg*RT + j;
        RowOff o = rowoff(r < R ? r : R-1);
        roE[j] = o.e;
        if constexpr (EMB){
          ulonglong2 eh = ((const ulonglong2*)(g_embH + o.bit*HD))[hq];
          acc[j].x = fadd2(bb1p.x, eh.x);
          acc[j].y = fadd2(bb1p.y, eh.y);
        } else {
          acc[j] = bb1p;
        }
      }
      ulonglong2 w0 = ((const ulonglong2*)(W1       ))[hq];
      ulonglong2 w1 = ((const ulonglong2*)(W1 + 1*HD))[hq];
      ulonglong2 w2 = ((const ulonglong2*)(W1 + 2*HD))[hq];
      ulonglong2 w3 = ((const ulonglong2*)(W1 + 3*HD))[hq];
      for (int k4 = 0; k4 < K; k4 += 4){
        const int k4n = (k4 + 4 < K) ? k4 + 4 : 0;   // clamped prefetch
        ulonglong2 n0 = ((const ulonglong2*)(W1 + (k4n  )*HD))[hq];
        ulonglong2 n1 = ((const ulonglong2*)(W1 + (k4n+1)*HD))[hq];
        ulonglong2 n2 = ((const ulonglong2*)(W1 + (k4n+2)*HD))[hq];
        ulonglong2 n3 = ((const ulonglong2*)(W1 + (k4n+3)*HD))[hq];
        #pragma unroll
        for (int j=0;j<RT;j++){
          float4 xv = *(const float4*)&sm.EALL[roE[j] + k4];
          u64t d0 = pack2(xv.x); ffma2(acc[j].x, w0.x, d0); ffma2(acc[j].y, w0.y, d0);
          u64t d1 = pack2(xv.y); ffma2(acc[j].x, w1.x, d1); ffma2(acc[j].y, w1.y, d1);
          u64t d2 = pack2(xv.z); ffma2(acc[j].x, w2.x, d2); ffma2(acc[j].y, w2.y, d2);
          u64t d3 = pack2(xv.w); ffma2(acc[j].x, w3.x, d3); ffma2(acc[j].y, w3.y, d3);
        }
        w0 = n0; w1 = n1; w2 = n2; w3 = n3;
      }
      #pragma unroll
      for (int j=0;j<RT;j++){
        float4 v;
        float f0,f1,f2,f3;
        unpack2(acc[j].x, f0, f1);
        unpack2(acc[j].y, f2, f3);
        v.x = fmaxf(f0,0.f); v.y = fmaxf(f1,0.f);
        v.z = fmaxf(f2,0.f); v.w = fmaxf(f3,0.f);
        *(float4*)&sm.Bh[(rg*RT + j)*BST + 4*hq] = v;
      }
    }
    __syncthreads();
    // ---- layer 2 (256 -> 64), 2 rows/thread, 32 cols/warp, prefetch ----
    {
      ulonglong2 a0 = bb2p, a1 = bb2p;
      ulonglong2 w0 = ((const ulonglong2*)(W2       ))[wi];
      ulonglong2 w1 = ((const ulonglong2*)(W2 + 1*64))[wi];
      ulonglong2 w2 = ((const ulonglong2*)(W2 + 2*64))[wi];
      ulonglong2 w3 = ((const ulonglong2*)(W2 + 3*64))[wi];
      for (int k4 = 0; k4 < HD; k4 += 4){
        const int k4n = (k4 + 4 < HD) ? k4 + 4 : 0;
        ulonglong2 n0 = ((const ulonglong2*)(W2 + (k4n  )*64))[wi];
        ulonglong2 n1 = ((const ulonglong2*)(W2 + (k4n+1)*64))[wi];
        ulonglong2 n2 = ((const ulonglong2*)(W2 + (k4n+2)*64))[wi];
        ulonglong2 n3 = ((const ulonglong2*)(W2 + (k4n+3)*64))[wi];
        float4 xa = *(const float4*)&sm.Bh[rr*BST + k4];
        float4 xb = *(const float4*)&sm.Bh[(rr+32)*BST + k4];
        u64t d;
        d = pack2(xa.x); ffma2(a0.x, w0.x, d); ffma2(a0.y, w0.y, d);
        d = pack2(xa.y); ffma2(a0.x, w1.x, d); ffma2(a0.y, w1.y, d);
        d = pack2(xa.z); ffma2(a0.x, w2.x, d); ffma2(a0.y, w2.y, d);
        d = pack2(xa.w); ffma2(a0.x, w3.x, d); ffma2(a0.y, w3.y, d);
        d = pack2(xb.x); ffma2(a1.x, w0.x, d); ffma2(a1.y, w0.y, d);
        d = pack2(xb.y); ffma2(a1.x, w1.x, d); ffma2(a1.y, w1.y, d);
        d = pack2(xb.z); ffma2(a1.x, w2.x, d); ffma2(a1.y, w2.y, d);
        d = pack2(xb.w); ffma2(a1.x, w3.x, d); ffma2(a1.y, w3.y, d);
        w0 = n0; w1 = n1; w2 = n2; w3 = n3;
      }
      float4 v;
      if (r0 + rr < R){
        unpack2(a0.x, v.x, v.y); unpack2(a0.y, v.z, v.w);
        *(float4*)&sm.EALL[EoutOff + (r0+rr)*64 + ch*32 + cq8*4] = v;
      }
      if (r0 + rr + 32 < R){
        unpack2(a1.x, v.x, v.y); unpack2(a1.y, v.z, v.w);
        *(float4*)&sm.EALL[EoutOff + (r0+rr+32)*64 + ch*32 + cq8*4] = v;
      }
    }
    __syncthreads();
  }
}

// ================= SMALL path: R < 64 =================
template<int K, bool EMB, int RT, typename RowOffF>
__device__ void run_mlp_small(Smem& sm, int R,
    const float* __restrict__ W1, const float* __restrict__ b1,
    const float* __restrict__ W2, const float* __restrict__ b2,
    int EoutOff, RowOffF rowoff)
{
  constexpr int TILE  = 8*RT;
  constexpr int KS    = 4/RT;
  constexpr int KC    = HD/KS;
  constexpr int TPG   = 128*RT;

  float* Part = &sm.Bh[32*BST];    // alias: small path uses Bh rows 0..31 only

  const int tid = threadIdx.x;
  const int hq  = tid & 63;
  const int rg  = tid >> 6;
  const int g   = tid / TPG;
  const int loc = tid - g*TPG;
  // layer-2 remap within group: 32 cols/warp, duplicated rows
  const int cq8 = loc & 7;
  const int rr  = (loc >> 3) & (TILE - 1);
  const int ch  = loc / (8*TILE);      // 0..1
  const int wi  = ch*8 + cq8;
  const ulonglong2 bb1p = ((const ulonglong2*)b1)[hq];
  const ulonglong2 bb2p = ((const ulonglong2*)b2)[wi];

  for (int r0 = 0; r0 < R; r0 += TILE) {
    // ---- layer 1 ----
    {
      ulonglong2 acc[RT];
      int roE[RT];
      #pragma unroll
      for (int j=0;j<RT;j++){
        int r = r0 + rg*RT + j;
        RowOff o = rowoff(r < R ? r : R-1);
        roE[j] = o.e;
        if constexpr (EMB){
          ulonglong2 eh = ((const ulonglong2*)(g_embH + o.bit*HD))[hq];
          acc[j].x = fadd2(bb1p.x, eh.x);
          acc[j].y = fadd2(bb1p.y, eh.y);
        } else {
          acc[j] = bb1p;
        }
      }
      #pragma unroll 2
      for (int k4 = 0; k4 < K; k4 += 4){
        ulonglong2 w0 = ((const ulonglong2*)(W1 + (k4  )*HD))[hq];
        ulonglong2 w1 = ((const ulonglong2*)(W1 + (k4+1)*HD))[hq];
        ulonglong2 w2 = ((const ulonglong2*)(W1 + (k4+2)*HD))[hq];
        ulonglong2 w3 = ((const ulonglong2*)(W1 + (k4+3)*HD))[hq];
        #pragma unroll
        for (int j=0;j<RT;j++){
          float4 xv = *(const float4*)&sm.EALL[roE[j] + k4];
          u64t d0 = pack2(xv.x); ffma2(acc[j].x, w0.x, d0); ffma2(acc[j].y, w0.y, d0);
          u64t d1 = pack2(xv.y); ffma2(acc[j].x, w1.x, d1); ffma2(acc[j].y, w1.y, d1);
          u64t d2 = pack2(xv.z); ffma2(acc[j].x, w2.x, d2); ffma2(acc[j].y, w2.y, d2);
          u64t d3 = pack2(xv.w); ffma2(acc[j].x, w3.x, d3); ffma2(acc[j].y, w3.y, d3);
        }
      }
      #pragma unroll
      for (int j=0;j<RT;j++){
        float4 v;
        float f0,f1,f2,f3;
        unpack2(acc[j].x, f0, f1);
        unpack2(acc[j].y, f2, f3);
        v.x = fmaxf(f0,0.f); v.y = fmaxf(f1,0.f);
        v.z = fmaxf(f2,0.f); v.w = fmaxf(f3,0.f);
        *(float4*)&sm.Bh[(rg*RT + j)*BST + 4*hq] = v;
      }
    }
    __syncthreads();
    // ---- layer 2, k-split across KS groups, remapped cols, prefetch ----
    {
      ulonglong2 acc2;
      if (KS == 1 || g == 0) acc2 = bb2p;
      else { acc2.x = 0ull; acc2.y = 0ull; }
      const float* Bb = &sm.Bh[rr*BST + g*KC];
      const float* W2b = W2 + g*KC*64;
      ulonglong2 w0 = ((const ulonglong2*)(W2b       ))[wi];
      ulonglong2 w1 = ((const ulonglong2*)(W2b + 1*64))[wi];
      ulonglong2 w2 = ((const ulonglong2*)(W2b + 2*64))[wi];
      ulonglong2 w3 = ((const ulonglong2*)(W2b + 3*64))[wi];
      for (int k4 = 0; k4 < KC; k4 += 4){
        const int k4n = (k4 + 4 < KC) ? k4 + 4 : 0;
        ulonglong2 n0 = ((const ulonglong2*)(W2b + (k4n  )*64))[wi];
        ulonglong2 n1 = ((const ulonglong2*)(W2b + (k4n+1)*64))[wi];
        ulonglong2 n2 = ((const ulonglong2*)(W2b + (k4n+2)*64))[wi];
        ulonglong2 n3 = ((const ulonglong2*)(W2b + (k4n+3)*64))[wi];
        float4 xv = *(const float4*)&Bb[k4];
        u64t d;
        d = pack2(xv.x); ffma2(acc2.x, w0.x, d); ffma2(acc2.y, w0.y, d);
        d = pack2(xv.y); ffma2(acc2.x, w1.x, d); ffma2(acc2.y, w1.y, d);
        d = pack2(xv.z); ffma2(acc2.x, w2.x, d); ffma2(acc2.y, w2.y, d);
        d = pack2(xv.w); ffma2(acc2.x, w3.x, d); ffma2(acc2.y, w3.y, d);
        w0 = n0; w1 = n1; w2 = n2; w3 = n3;
      }
      float4 acc;
      unpack2(acc2.x, acc.x, acc.y);
      unpack2(acc2.y, acc.z, acc.w);
      if constexpr (KS == 1){
        if (r0 + rr < R)
          *(float4*)&sm.EALL[EoutOff + (r0+rr)*64 + ch*32 + cq8*4] = acc;
      } else {
        *(float4*)&Part[(g*TILE + rr)*64 + ch*32 + cq8*4] = acc;
        __syncthreads();
        if (tid < TPG && r0 + rr < R){
          float4 s = *(const float4*)&Part[rr*64 + ch*32 + cq8*4];
          #pragma unroll
          for (int gg = 1; gg < KS; gg++){
            float4 p = *(const float4*)&Part[(gg*TILE + rr)*64 + ch*32 + cq8*4];
            s.x += p.x; s.y += p.y; s.z += p.z; s.w += p.w;
          }
          *(float4*)&sm.EALL[EoutOff + (r0+rr)*64 + ch*32 + cq8*4] = s;
        }
      }
    }
    __syncthreads();
  }
}

// broadcast list 0 -> lists 1..7; cnt = half*64 (pow2)
__device__ void bcast_lists(Smem& sm, int off, int cnt)
{
  float4* E4 = (float4*)&sm.EALL[off];
  const int cnt4 = cnt >> 2;
  for (int i = threadIdx.x; i < 7*cnt4; i += NT)
    E4[cnt4 + i] = E4[i & (cnt4 - 1)];
  __syncthreads();
}

// ---------------- leaf ----------------
__device__ void do_leaf(Smem& sm, int leaf, const Params& P, const int* __restrict__ f)
{
  const int tid = threadIdx.x, warp = tid>>5, lane = tid&31;
  constexpr int O6 = OOFFc(6);
  if (warp < 8) {
    const float* e = &sm.EALL[EO6 + warp*64];
    float z0 = 0.f, z1 = 0.f;
    for (int c = lane; c < 64; c += 32){
      float v = e[c];
      z0 += v*P.Wllr[c*2];
      z1 += v*P.Wllr[c*2+1];
    }
    #pragma unroll
    for (int off=16; off; off>>=1){
      z0 += __shfl_xor_sync(0xffffffffu, z0, off);
      z1 += __shfl_xor_sync(0xffffffffu, z1, off);
    }
    if (lane == 0){
      z0 += P.bllr[0]; z1 += P.bllr[1];
      float m  = fmaxf(z0, z1);
      float e0 = expf(z0 - m), e1 = expf(z1 - m);
      float p1 = e1 / (e0 + e1);
      p1 = fminf(fmaxf(p1, 1e-6f), 1.0f - 1e-6f);
      float llr = logf(p1) - logf(1.0f - p1);
      sm.Llr[warp] = llr;
      sm.Abs[warp] = fabsf(llr);
      sm.Hd[warp]  = (z1 > z0) ? 1 : 0;
    }
  }
  __syncthreads();
  if (warp == 0){
    const int fv = f[leaf];
    if (fv != 2){
      if (lane < 8){
        sm.Xout[O6+lane] = fv; sm.Uout[O6+lane] = fv;
        sm.Lout[O6+lane] = sm.Llr[lane];
        if (sm.Hd[lane] != fv) sm.Pm[lane] += sm.Abs[lane];
        sm.Ret[lane] = lane;
      }
    } else {
      float pd = 1e30f; int hd = 0;
      if (lane < 16){
        int l = lane & 7;
        if (lane < 8){ pd = sm.Pm[l];             hd = sm.Hd[l];     }
        else         { pd = sm.Pm[l] + sm.Abs[l]; hd = 1 - sm.Hd[l]; }
      }
      int rank = 0;
      #pragma unroll
      for (int q = 0; q < 16; q++){
        float pq = __shfl_sync(0xffffffffu, pd, q);
        if (pq < pd || (pq == pd && q < lane)) rank++;
      }
      unsigned surv = __ballot_sync(0xffffffffu, lane < 16 && rank < 8);
      if (lane < 16 && rank < 8){
        int pos = __popc(surv & ((1u<<lane) - 1u));
        sm.Xout[O6+pos] = hd; sm.Uout[O6+pos] = hd;
        sm.PmNew[pos]   = pd;
        sm.Ret[pos]     = lane & 7;
      }
      __syncwarp();
      if (lane < 8){ sm.Pm[lane] = sm.PmNew[lane]; sm.Lout[O6+lane] = sm.Llr[lane]; }
    }
  }
  __syncthreads();
}

// ---------------- tree recursion ----------------
template<int NK, int LVL>
__device__ void decode_node(Smem& sm, int leaf_base, const Params& P, const int* __restrict__ f)
{
  if constexpr (NK == 1) {
    do_leaf(sm, leaf_base, P, f);
  } else {
    constexpr int half = NK/2;
    constexpr int R    = 8*half;
    constexpr bool BIG = (half >= 8);                              // R >= 64
    constexpr int RTF  = (half >= 4) ? 4 : half;                   // small full calls
    constexpr int RTU  = (half >= 32) ? 4 : (half >= 16) ? 2 : 1;  // uniform calls
    constexpr int EKo  = EOlvl(LVL);
    constexpr int ENo  = EOlvl(LVL+1);
    constexpr int ON   = OOFFc(LVL+1);
    constexpr int OK   = OOFFc(LVL);
    constexpr int SK   = SOFFc(LVL);
    constexpr bool L0  = (LVL == 0);

    auto chkRow = [&](int r)->RowOff {
      int l = r / half, t = r - l*half;
      int e = L0 ? (EO0 + 2*t*64) : (EKo + (l*NK + 2*t)*64);
      return {e, 0};
    };
    const bool uc = (sm.first_info >= leaf_base);
    if (uc){
      run_mlp_small<2*DE, false, RTU>(sm, half, P.Wc1, P.bc1, P.Wc2, P.bc2, ENo, chkRow);
      bcast_lists(sm, ENo, half*64);
    } else if constexpr (BIG){
      run_mlp_big<2*DE, false>(sm, R, P.Wc1, P.bc1, P.Wc2, P.bc2, ENo, chkRow);
    } else {
      run_mlp_small<2*DE, false, RTF>(sm, R, P.Wc1, P.bc1, P.Wc2, P.bc2, ENo, chkRow);
    }

    decode_node<half, LVL+1>(sm, leaf_base, P, f);

    __syncthreads();
    for (int idx = threadIdx.x; idx < R; idx += NT){
      sm.U1[SK+idx]  = sm.Uout[ON+idx];
      sm.X1[SK+idx]  = sm.Xout[ON+idx];
      sm.L1f[SK+idx] = sm.Lout[ON+idx];
    }
    if (threadIdx.x < 8) sm.Ord1[LVL*8 + threadIdx.x] = sm.Ret[threadIdx.x];
    __syncthreads();

    auto bitRow = [&](int r)->RowOff {
      int l = r / half, t = r - l*half;
      int ol = sm.Ord1[LVL*8 + l];
      int e = L0 ? (EO0 + 2*t*64) : (EKo + (ol*NK + 2*t)*64);
      int bit = sm.X1[SK + l*half + t];
      return {e, bit};
    };
    const bool ub = (sm.first_info >= leaf_base + half);
    if (ub){
      run_mlp_small<2*DE, true, RTU>(sm, half, P.Wb1, P.bb1, P.Wb2, P.bb2, ENo, bitRow);
      bcast_lists(sm, ENo, half*64);
    } else if constexpr (BIG){
      run_mlp_big<2*DE, true>(sm, R, P.Wb1, P.bb1, P.Wb2, P.bb2, ENo, bitRow);
    } else {
      run_mlp_small<2*DE, true, RTF>(sm, R, P.Wb1, P.bb1, P.Wb2, P.bb2, ENo, bitRow);
    }

    decode_node<half, LVL+1>(sm, leaf_base + half, P, f);

    __syncthreads();
    if (threadIdx.x < 8) sm.Ord2[threadIdx.x] = sm.Ret[threadIdx.x];
    __syncthreads();
    for (int idx = threadIdx.x; idx < R; idx += NT){
      int l = idx / half, t = idx - l*half;
      int o2 = sm.Ord2[l];
      int   u1 = sm.U1[SK + o2*half + t];
      int   x1 = sm.X1[SK + o2*half + t];
      float l1 = sm.L1f[SK + o2*half + t];
      int   u2 = sm.Uout[ON + idx];
      int   x2 = sm.Xout[ON + idx];
      float l2 = sm.Lout[ON + idx];
      sm.Uout[OK + l*NK + t]        = u1;
      sm.Uout[OK + l*NK + half + t] = u2;
      sm.Lout[OK + l*NK + t]        = l1;
      sm.Lout[OK + l*NK + half + t] = l2;
      sm.Xout[OK + l*NK + 2*t]      = (x1 + x2) & 1;
      sm.Xout[OK + l*NK + 2*t + 1]  = x2;
    }
    __syncthreads();
    if (threadIdx.x < 8) sm.Ret[threadIdx.x] = sm.Ord1[LVL*8 + sm.Ord2[threadIdx.x]];
    __syncthreads();
  }
}

__global__ void __launch_bounds__(NT, 1)
scl_kernel(Params P, const float* __restrict__ y, const int* __restrict__ f,
           float* __restrict__ out, int out_size)
{
  extern __shared__ char smem_raw[];
  Smem& sm = *reinterpret_cast<Smem*>(smem_raw);
  const int b = blockIdx.x, tid = threadIdx.x;
  if (tid < 8) sm.Pm[tid] = (tid == 0) ? 0.f : 1e8f;
  if (tid == 0){
    int fi = 64;
    for (int i = 0; i < 64; i++) if (f[i] == 2){ fi = i; break; }
    sm.first_info = fi;
  }
  if (tid < 256) sm.EALL[YO + tid] = y[b*256 + tid];    // obs input rows

  // precompute embH[bit][h] = sum_k W_bit1[128+k][h] * emb[bit][k]
  // (identical values in every block -> benign concurrent writes)
  {
    int bit = tid >> 8, h = tid & 255;
    float s = 0.f;
    #pragma unroll
    for (int k = 0; k < DU; k++)
      s = fmaf(P.Wb1[(128+k)*HD + h], P.emb[bit*DU + k], s);
    g_embH[bit*HD + h] = s;
  }
  __syncthreads();

  // observation MLP (K=4) -> E0 (single list), R=64 -> big path
  run_mlp_big<4, false>(sm, 64, P.Wo1, P.bo1, P.Wo2, P.bo2, EO0,
    [&](int r)->RowOff { return {YO + r*4, 0}; });

  decode_node<64, 0>(sm, 0, P, f);

  if (tid == 0){
    int best = 0; float bv = sm.Pm[0];
    for (int l=1;l<8;l++) if (sm.Pm[l] < bv){ bv = sm.Pm[l]; best = l; }
    sm.Ord2[0] = best;
  }
  __syncthreads();
  const int best = sm.Ord2[0];

  if (out_size >= 8192 + 65536){
    for (int t = tid; t < 64; t += NT)
      out[b*64 + t] = (float)sm.Uout[best*64 + t];
    for (int idx = tid; idx < 512; idx += NT)
      out[8192 + b*512 + idx] = sm.Lout[idx];
  } else if (out_size == 8192){
    for (int t = tid; t < 64; t += NT)
      out[b*64 + t] = (float)sm.Uout[best*64 + t];
  } else {
    for (int idx = tid; idx < 512 && (b*512 + idx) < out_size; idx += NT)
      out[b*512 + idx] = sm.Lout[idx];
  }
}

extern "C" void kernel_launch(void* const* d_in, const int* in_sizes, int n_in,
                              void* d_out, int out_size)
{
  Params P;
  const float* y  = (const float*)d_in[0];
  const int*   f  = (const int*)  d_in[1];
  P.Wo1  = (const float*)d_in[2];
  P.bo1  = (const float*)d_in[3];
  P.Wo2  = (const float*)d_in[4];
  P.bo2  = (const float*)d_in[5];
  P.Wc1  = (const float*)d_in[6];
  P.bc1  = (const float*)d_in[7];
  P.Wc2  = (const float*)d_in[8];
  P.bc2  = (const float*)d_in[9];
  P.Wb1  = (const float*)d_in[10];
  P.bb1  = (const float*)d_in[11];
  P.Wb2  = (const float*)d_in[12];
  P.bb2  = (const float*)d_in[13];
  P.Wllr = (const float*)d_in[14];
  P.bllr = (const float*)d_in[15];
  P.emb  = (const float*)d_in[16];

  cudaFuncSetAttribute(scl_kernel, cudaFuncAttributeMaxDynamicSharedMemorySize,
                       (int)sizeof(Smem));
  scl_kernel<<<NB, NT, sizeof(Smem)>>>(P, y, f, (float*)d_out, out_size);
}

// round 16
// speedup vs baseline: 1.0054x; 1.0054x over previous
#include <cuda_runtime.h>

// SCL polar decoder, neural-MLP variant. Round 15 = Round 14 + L1-capacity
// recovery: the 64KB E1 activation buffer moves to global (g_E1, L2), with a
// 33KB smem staging tile (Astage) for level-1 MLP inputs. Smem drops 231.6KB
// -> 199.9KB, leaving ~56KB unified L1D so the hot W2 (64KB) weight matrices
// cache instead of hitting L2 every load. Inner loops byte-identical
// (staging is a pure copy) -> bit-identical results.
//  - embH precompute; BIG TILE=64/RT=8 + prefetch both layers; SMALL RT{4,2,1}
//  - FFMA2 packed math; uniform-list elimination

#define NLIST 8
#define DE    64
#define HD    256
#define DU    16
#define NB    128
#define NT    512

typedef unsigned long long u64t;

__device__ float g_embH[2*HD];           // identical values from every block
__device__ float g_E1[NB][8*32*64];      // level-1 E tensor (per batch)

struct Params {
  const float *Wo1, *bo1, *Wo2, *bo2;
  const float *Wc1, *bc1, *Wc2, *bc2;
  const float *Wb1, *bb1, *Wb2, *bb2;
  const float *Wllr, *bllr, *emb;
};

// E buffer offsets inside the flat smem array (floats). E1 lives in global.
#define EO2   0        // 8*16*64 = 8192
#define EO3   8192     // 4096
#define EO4   12288    // 2048
#define EO5   14336    // 1024
#define EO6   15360    // 512
#define EO0   15872    // single list: 64*64 = 4096
#define YO    19968    // obs input staging: 256
#define EALLN 20224

#define BST   260      // Bh row stride
#define AST   132      // Astage row stride (K=128 + 4)

__host__ __device__ constexpr int EOlvl(int L){
  return (L==0)?EO0:(L==2)?EO2:(L==3)?EO3:(L==4)?EO4:(L==5)?EO5:(L==6)?EO6:0;
}
__host__ __device__ constexpr int OOFFc(int k){ int o=0; for(int i=0;i<k;i++) o += 8*(64>>i); return o; }
__host__ __device__ constexpr int SOFFc(int k){ int o=0; for(int i=0;i<k;i++) o += 4*(64>>i); return o; }

struct __align__(16) Smem {
  float EALL[EALLN];   // E levels 0,2..6 + y staging       (80896 B)
  float Astage[64*AST];// staged global activation tile     (33792 B)
  float Bh[64*BST];    // hidden tile [r][h]                 (66560 B)
  int   Uout[1016];
  int   Xout[1016];
  float Lout[1016];
  int   U1[504];
  int   X1[504];
  float L1f[504];
  int   Ord1[48];
  int   Ord2[8];
  int   Ret[8];
  float Pm[8];
  float PmNew[8];
  float Llr[8];
  float Abs[8];
  int   Hd[8];
  int   first_info;
};

struct RowOff { int e; int bit; };

// ---- packed f32x2 helpers ----
__device__ __forceinline__ u64t pack2(float x){
  u64t r;
  asm("mov.b64 %0, {%1, %1};" : "=l"(r) : "f"(x));
  return r;
}
__device__ __forceinline__ void ffma2(u64t& acc, u64t a, u64t b){
  asm("fma.rn.f32x2 %0, %1, %2, %0;" : "+l"(acc) : "l"(a), "l"(b));
}
__device__ __forceinline__ u64t fadd2(u64t a, u64t b){
  u64t r;
  asm("add.rn.f32x2 %0, %1, %2;" : "=l"(r) : "l"(a), "l"(b));
  return r;
}
__device__ __forceinline__ void unpack2(u64t v, float& lo, float& hi){
  asm("mov.b64 {%0, %1}, %2;" : "=f"(lo), "=f"(hi) : "l"(v));
}

// ================= BIG path: R >= 64, TILE=64, RT=8 =================
// ING: activations staged from Eg_in (global).  OUTG: outputs go to Eg_out.
template<int K, bool EMB, bool ING, bool OUTG, typename RowOffF>
__device__ void run_mlp_big(Smem& sm, int R,
    const float* __restrict__ W1, const float* __restrict__ b1,
    const float* __restrict__ W2, const float* __restrict__ b2,
    int EoutOff, const float* __restrict__ Eg_in, float* __restrict__ Eg_out,
    RowOffF rowoff)
{
  constexpr int RT    = 8;
  constexpr int TILE  = 64;
  static_assert(!ING || K == 128, "staging assumes K=128");

  const int tid = threadIdx.x;
  const int hq  = tid & 63;
  const int rg  = tid >> 6;        // 0..7
  const int cq8 = tid & 7;
  const int rr  = (tid >> 3) & 31;
  const int ch  = tid >> 8;
  const int wi  = ch*8 + cq8;
  const ulonglong2 bb1p = ((const ulonglong2*)b1)[hq];
  const ulonglong2 bb2p = ((const ulonglong2*)b2)[wi];

  for (int r0 = 0; r0 < R; r0 += TILE) {
    if constexpr (ING){
      // stage TILE rows (clamped) of global activations into Astage
      for (int idx = tid; idx < TILE*32; idx += NT){
        int r = idx >> 5, c = idx & 31;
        int ra = r0 + r;
        RowOff o = rowoff(ra < R ? ra : R-1);
        *(float4*)&sm.Astage[r*AST + 4*c] = *(const float4*)&Eg_in[o.e + 4*c];
      }
      __syncthreads();
    }
    // ---- layer 1: RT=8 row reuse, double-buffered weight prefetch ----
    {
      const float* Eact = ING ? sm.Astage : sm.EALL;
      ulonglong2 acc[RT];
      int roE[RT];
      #pragma unroll
      for (int j=0;j<RT;j++){
        int r = r0 + rg*RT + j;
        RowOff o = rowoff(r < R ? r : R-1);
        roE[j] = ING ? (rg*RT + j)*AST : o.e;
        if constexpr (EMB){
          ulonglong2 eh = ((const ulonglong2*)(g_embH + o.bit*HD))[hq];
          acc[j].x = fadd2(bb1p.x, eh.x);
          acc[j].y = fadd2(bb1p.y, eh.y);
        } else {
          acc[j] = bb1p;
        }
      }
      ulonglong2 w0 = ((const ulonglong2*)(W1       ))[hq];
      ulonglong2 w1 = ((const ulonglong2*)(W1 + 1*HD))[hq];
      ulonglong2 w2 = ((const ulonglong2*)(W1 + 2*HD))[hq];
      ulonglong2 w3 = ((const ulonglong2*)(W1 + 3*HD))[hq];
      for (int k4 = 0; k4 < K; k4 += 4){
        const int k4n = (k4 + 4 < K) ? k4 + 4 : 0;   // clamped prefetch
        ulonglong2 n0 = ((const ulonglong2*)(W1 + (k4n  )*HD))[hq];
        ulonglong2 n1 = ((const ulonglong2*)(W1 + (k4n+1)*HD))[hq];
        ulonglong2 n2 = ((const ulonglong2*)(W1 + (k4n+2)*HD))[hq];
        ulonglong2 n3 = ((const ulonglong2*)(W1 + (k4n+3)*HD))[hq];
        #pragma unroll
        for (int j=0;j<RT;j++){
          float4 xv = *(const float4*)&Eact[roE[j] + k4];
          u64t d0 = pack2(xv.x); ffma2(acc[j].x, w0.x, d0); ffma2(acc[j].y, w0.y, d0);
          u64t d1 = pack2(xv.y); ffma2(acc[j].x, w1.x, d1); ffma2(acc[j].y, w1.y, d1);
          u64t d2 = pack2(xv.z); ffma2(acc[j].x, w2.x, d2); ffma2(acc[j].y, w2.y, d2);
          u64t d3 = pack2(xv.w); ffma2(acc[j].x, w3.x, d3); ffma2(acc[j].y, w3.y, d3);
        }
        w0 = n0; w1 = n1; w2 = n2; w3 = n3;
      }
      #pragma unroll
      for (int j=0;j<RT;j++){
        float4 v;
        float f0,f1,f2,f3;
        unpack2(acc[j].x, f0, f1);
        unpack2(acc[j].y, f2, f3);
        v.x = fmaxf(f0,0.f); v.y = fmaxf(f1,0.f);
        v.z = fmaxf(f2,0.f); v.w = fmaxf(f3,0.f);
        *(float4*)&sm.Bh[(rg*RT + j)*BST + 4*hq] = v;
      }
    }
    __syncthreads();
    // ---- layer 2 (256 -> 64), 2 rows/thread, prefetch ----
    {
      ulonglong2 a0 = bb2p, a1 = bb2p;
      ulonglong2 w0 = ((const ulonglong2*)(W2       ))[wi];
      ulonglong2 w1 = ((const ulonglong2*)(W2 + 1*64))[wi];
      ulonglong2 w2 = ((const ulonglong2*)(W2 + 2*64))[wi];
      ulonglong2 w3 = ((const ulonglong2*)(W2 + 3*64))[wi];
      for (int k4 = 0; k4 < HD; k4 += 4){
        const int k4n = (k4 + 4 < HD) ? k4 + 4 : 0;
        ulonglong2 n0 = ((const ulonglong2*)(W2 + (k4n  )*64))[wi];
        ulonglong2 n1 = ((const ulonglong2*)(W2 + (k4n+1)*64))[wi];
        ulonglong2 n2 = ((const ulonglong2*)(W2 + (k4n+2)*64))[wi];
        ulonglong2 n3 = ((const ulonglong2*)(W2 + (k4n+3)*64))[wi];
        float4 xa = *(const float4*)&sm.Bh[rr*BST + k4];
        float4 xb = *(const float4*)&sm.Bh[(rr+32)*BST + k4];
        u64t d;
        d = pack2(xa.x); ffma2(a0.x, w0.x, d); ffma2(a0.y, w0.y, d);
        d = pack2(xa.y); ffma2(a0.x, w1.x, d); ffma2(a0.y, w1.y, d);
        d = pack2(xa.z); ffma2(a0.x, w2.x, d); ffma2(a0.y, w2.y, d);
        d = pack2(xa.w); ffma2(a0.x, w3.x, d); ffma2(a0.y, w3.y, d);
        d = pack2(xb.x); ffma2(a1.x, w0.x, d); ffma2(a1.y, w0.y, d);
        d = pack2(xb.y); ffma2(a1.x, w1.x, d); ffma2(a1.y, w1.y, d);
        d = pack2(xb.z); ffma2(a1.x, w2.x, d); ffma2(a1.y, w2.y, d);
        d = pack2(xb.w); ffma2(a1.x, w3.x, d); ffma2(a1.y, w3.y, d);
        w0 = n0; w1 = n1; w2 = n2; w3 = n3;
      }
      float4 v;
      if (r0 + rr < R){
        unpack2(a0.x, v.x, v.y); unpack2(a0.y, v.z, v.w);
        if constexpr (OUTG) *(float4*)&Eg_out[(r0+rr)*64 + ch*32 + cq8*4] = v;
        else *(float4*)&sm.EALL[EoutOff + (r0+rr)*64 + ch*32 + cq8*4] = v;
      }
      if (r0 + rr + 32 < R){
        unpack2(a1.x, v.x, v.y); unpack2(a1.y, v.z, v.w);
        if constexpr (OUTG) *(float4*)&Eg_out[(r0+rr+32)*64 + ch*32 + cq8*4] = v;
        else *(float4*)&sm.EALL[EoutOff + (r0+rr+32)*64 + ch*32 + cq8*4] = v;
      }
    }
    __syncthreads();
  }
}

// ================= SMALL path: R < 64 =================
template<int K, bool EMB, int RT, bool ING, bool OUTG, typename RowOffF>
__device__ void run_mlp_small(Smem& sm, int R,
    const float* __restrict__ W1, const float* __restrict__ b1,
    const float* __restrict__ W2, const float* __restrict__ b2,
    int EoutOff, const float* __restrict__ Eg_in, float* __restrict__ Eg_out,
    RowOffF rowoff)
{
  constexpr int TILE  = 8*RT;
  constexpr int KS    = 4/RT;
  constexpr int KC    = HD/KS;
  constexpr int TPG   = 128*RT;
  static_assert(!ING || K == 128, "staging assumes K=128");

  float* Part = &sm.Bh[32*BST];    // alias: small path uses Bh rows 0..31 only

  const int tid = threadIdx.x;
  const int hq  = tid & 63;
  const int rg  = tid >> 6;
  const int g   = tid / TPG;
  const int loc = tid - g*TPG;
  const int cq8 = loc & 7;
  const int rr  = (loc >> 3) & (TILE - 1);
  const int ch  = loc / (8*TILE);
  const int wi  = ch*8 + cq8;
  const ulonglong2 bb1p = ((const ulonglong2*)b1)[hq];
  const ulonglong2 bb2p = ((const ulonglong2*)b2)[wi];

  for (int r0 = 0; r0 < R; r0 += TILE) {
    if constexpr (ING){
      for (int idx = tid; idx < TILE*32; idx += NT){
        int r = idx >> 5, c = idx & 31;
        int ra = r0 + r;
        RowOff o = rowoff(ra < R ? ra : R-1);
        *(float4*)&sm.Astage[r*AST + 4*c] = *(const float4*)&Eg_in[o.e + 4*c];
      }
      __syncthreads();
    }
    // ---- layer 1 ----
    {
      const float* Eact = ING ? sm.Astage : sm.EALL;
      ulonglong2 acc[RT];
      int roE[RT];
      #pragma unroll
      for (int j=0;j<RT;j++){
        int r = r0 + rg*RT + j;
        RowOff o = rowoff(r < R ? r : R-1);
        roE[j] = ING ? (rg*RT + j)*AST : o.e;
        if constexpr (EMB){
          ulonglong2 eh = ((const ulonglong2*)(g_embH + o.bit*HD))[hq];
          acc[j].x = fadd2(bb1p.x, eh.x);
          acc[j].y = fadd2(bb1p.y, eh.y);
        } else {
          acc[j] = bb1p;
        }
      }
      #pragma unroll 2
      for (int k4 = 0; k4 < K; k4 += 4){
        ulonglong2 w0 = ((const ulonglong2*)(W1 + (k4  )*HD))[hq];
        ulonglong2 w1 = ((const ulonglong2*)(W1 + (k4+1)*HD))[hq];
        ulonglong2 w2 = ((const ulonglong2*)(W1 + (k4+2)*HD))[hq];
        ulonglong2 w3 = ((const ulonglong2*)(W1 + (k4+3)*HD))[hq];
        #pragma unroll
        for (int j=0;j<RT;j++){
          float4 xv = *(const float4*)&Eact[roE[j] + k4];
          u64t d0 = pack2(xv.x); ffma2(acc[j].x, w0.x, d0); ffma2(acc[j].y, w0.y, d0);
          u64t d1 = pack2(xv.y); ffma2(acc[j].x, w1.x, d1); ffma2(acc[j].y, w1.y, d1);
          u64t d2 = pack2(xv.z); ffma2(acc[j].x, w2.x, d2); ffma2(acc[j].y, w2.y, d2);
          u64t d3 = pack2(xv.w); ffma2(acc[j].x, w3.x, d3); ffma2(acc[j].y, w3.y, d3);
        }
      }
      #pragma unroll
      for (int j=0;j<RT;j++){
        float4 v;
        float f0,f1,f2,f3;
        unpack2(acc[j].x, f0, f1);
        unpack2(acc[j].y, f2, f3);
        v.x = fmaxf(f0,0.f); v.y = fmaxf(f1,0.f);
        v.z = fmaxf(f2,0.f); v.w = fmaxf(f3,0.f);
        *(float4*)&sm.Bh[(rg*RT + j)*BST + 4*hq] = v;
      }
    }
    __syncthreads();
    // ---- layer 2, k-split across KS groups, prefetch ----
    {
      ulonglong2 acc2;
      if (KS == 1 || g == 0) acc2 = bb2p;
      else { acc2.x = 0ull; acc2.y = 0ull; }
      const float* Bb = &sm.Bh[rr*BST + g*KC];
      const float* W2b = W2 + g*KC*64;
      ulonglong2 w0 = ((const ulonglong2*)(W2b       ))[wi];
      ulonglong2 w1 = ((const ulonglong2*)(W2b + 1*64))[wi];
      ulonglong2 w2 = ((const ulonglong2*)(W2b + 2*64))[wi];
      ulonglong2 w3 = ((const ulonglong2*)(W2b + 3*64))[wi];
      for (int k4 = 0; k4 < KC; k4 += 4){
        const int k4n = (k4 + 4 < KC) ? k4 + 4 : 0;
        ulonglong2 n0 = ((const ulonglong2*)(W2b + (k4n  )*64))[wi];
        ulonglong2 n1 = ((const ulonglong2*)(W2b + (k4n+1)*64))[wi];
        ulonglong2 n2 = ((const ulonglong2*)(W2b + (k4n+2)*64))[wi];
        ulonglong2 n3 = ((const ulonglong2*)(W2b + (k4n+3)*64))[wi];
        float4 xv = *(const float4*)&Bb[k4];
        u64t d;
        d = pack2(xv.x); ffma2(acc2.x, w0.x, d); ffma2(acc2.y, w0.y, d);
        d = pack2(xv.y); ffma2(acc2.x, w1.x, d); ffma2(acc2.y, w1.y, d);
        d = pack2(xv.z); ffma2(acc2.x, w2.x, d); ffma2(acc2.y, w2.y, d);
        d = pack2(xv.w); ffma2(acc2.x, w3.x, d); ffma2(acc2.y, w3.y, d);
        w0 = n0; w1 = n1; w2 = n2; w3 = n3;
      }
      float4 acc;
      unpack2(acc2.x, acc.x, acc.y);
      unpack2(acc2.y, acc.z, acc.w);
      if constexpr (KS == 1){
        if (r0 + rr < R){
          if constexpr (OUTG) *(float4*)&Eg_out[(r0+rr)*64 + ch*32 + cq8*4] = acc;
          else *(float4*)&sm.EALL[EoutOff + (r0+rr)*64 + ch*32 + cq8*4] = acc;
        }
      } else {
        *(float4*)&Part[(g*TILE + rr)*64 + ch*32 + cq8*4] = acc;
        __syncthreads();
        if (tid < TPG && r0 + rr < R){
          float4 s = *(const float4*)&Part[rr*64 + ch*32 + cq8*4];
          #pragma unroll
          for (int gg = 1; gg < KS; gg++){
            float4 p = *(const float4*)&Part[(gg*TILE + rr)*64 + ch*32 + cq8*4];
            s.x += p.x; s.y += p.y; s.z += p.z; s.w += p.w;
          }
          if constexpr (OUTG) *(float4*)&Eg_out[(r0+rr)*64 + ch*32 + cq8*4] = s;
          else *(float4*)&sm.EALL[EoutOff + (r0+rr)*64 + ch*32 + cq8*4] = s;
        }
      }
    }
    __syncthreads();
  }
}

// broadcast list 0 -> lists 1..7 (smem variant); cnt = half*64 (pow2)
__device__ void bcast_lists(Smem& sm, int off, int cnt)
{
  float4* E4 = (float4*)&sm.EALL[off];
  const int cnt4 = cnt >> 2;
  for (int i = threadIdx.x; i < 7*cnt4; i += NT)
    E4[cnt4 + i] = E4[i & (cnt4 - 1)];
  __syncthreads();
}
// global variant (for E1)
__device__ void bcast_g(float* __restrict__ E, int cnt)
{
  float4* E4 = (float4*)E;
  const int cnt4 = cnt >> 2;
  for (int i = threadIdx.x; i < 7*cnt4; i += NT)
    E4[cnt4 + i] = E4[i & (cnt4 - 1)];
  __syncthreads();
}

// ---------------- leaf ----------------
__device__ void do_leaf(Smem& sm, int leaf, const Params& P, const int* __restrict__ f)
{
  const int tid = threadIdx.x, warp = tid>>5, lane = tid&31;
  constexpr int O6 = OOFFc(6);
  if (warp < 8) {
    const float* e = &sm.EALL[EO6 + warp*64];
    float z0 = 0.f, z1 = 0.f;
    for (int c = lane; c < 64; c += 32){
      float v = e[c];
      z0 += v*P.Wllr[c*2];
      z1 += v*P.Wllr[c*2+1];
    }
    #pragma unroll
    for (int off=16; off; off>>=1){
      z0 += __shfl_xor_sync(0xffffffffu, z0, off);
      z1 += __shfl_xor_sync(0xffffffffu, z1, off);
    }
    if (lane == 0){
      z0 += P.bllr[0]; z1 += P.bllr[1];
      float m  = fmaxf(z0, z1);
      float e0 = expf(z0 - m), e1 = expf(z1 - m);
      float p1 = e1 / (e0 + e1);
      p1 = fminf(fmaxf(p1, 1e-6f), 1.0f - 1e-6f);
      float llr = logf(p1) - logf(1.0f - p1);
      sm.Llr[warp] = llr;
      sm.Abs[warp] = fabsf(llr);
      sm.Hd[warp]  = (z1 > z0) ? 1 : 0;
    }
  }
  __syncthreads();
  if (warp == 0){
    const int fv = f[leaf];
    if (fv != 2){
      if (lane < 8){
        sm.Xout[O6+lane] = fv; sm.Uout[O6+lane] = fv;
        sm.Lout[O6+lane] = sm.Llr[lane];
        if (sm.Hd[lane] != fv) sm.Pm[lane] += sm.Abs[lane];
        sm.Ret[lane] = lane;
      }
    } else {
      float pd = 1e30f; int hd = 0;
      if (lane < 16){
        int l = lane & 7;
        if (lane < 8){ pd = sm.Pm[l];             hd = sm.Hd[l];     }
        else         { pd = sm.Pm[l] + sm.Abs[l]; hd = 1 - sm.Hd[l]; }
      }
      int rank = 0;
      #pragma unroll
      for (int q = 0; q < 16; q++){
        float pq = __shfl_sync(0xffffffffu, pd, q);
        if (pq < pd || (pq == pd && q < lane)) rank++;
      }
      unsigned surv = __ballot_sync(0xffffffffu, lane < 16 && rank < 8);
      if (lane < 16 && rank < 8){
        int pos = __popc(surv & ((1u<<lane) - 1u));
        sm.Xout[O6+pos] = hd; sm.Uout[O6+pos] = hd;
        sm.PmNew[pos]   = pd;
        sm.Ret[pos]     = lane & 7;
      }
      __syncwarp();
      if (lane < 8){ sm.Pm[lane] = sm.PmNew[lane]; sm.Lout[O6+lane] = sm.Llr[lane]; }
    }
  }
  __syncthreads();
}

// ---------------- tree recursion ----------------
template<int NK, int LVL>
__device__ void decode_node(Smem& sm, float* __restrict__ e1,
                            int leaf_base, const Params& P, const int* __restrict__ f)
{
  if constexpr (NK == 1) {
    do_leaf(sm, leaf_base, P, f);
  } else {
    constexpr int half = NK/2;
    constexpr int R    = 8*half;
    constexpr bool BIG = (half >= 8);
    constexpr int RTF  = (half >= 4) ? 4 : half;
    constexpr int RTU  = (half >= 32) ? 4 : (half >= 16) ? 2 : 1;
    constexpr bool ING  = (LVL == 1);   // reads E1 (global)
    constexpr bool OUTG = (LVL == 0);   // writes E1 (global)
    constexpr int EKo  = EOlvl(LVL);
    constexpr int ENo  = (LVL == 0) ? 0 : EOlvl(LVL+1);
    constexpr int ON   = OOFFc(LVL+1);
    constexpr int OK   = OOFFc(LVL);
    constexpr int SK   = SOFFc(LVL);
    constexpr bool L0  = (LVL == 0);

    auto chkRow = [&](int r)->RowOff {
      int l = r / half, t = r - l*half;
      int e;
      if constexpr (L0)            e = EO0 + 2*t*64;           // smem E0
      else if constexpr (ING)      e = (l*NK + 2*t)*64;        // global E1
      else                         e = EKo + (l*NK + 2*t)*64;  // smem
      return {e, 0};
    };
    const bool uc = (sm.first_info >= leaf_base);
    if (uc){
      run_mlp_small<2*DE, false, RTU, ING, OUTG>(sm, half,
        P.Wc1, P.bc1, P.Wc2, P.bc2, ENo, e1, e1, chkRow);
      if constexpr (OUTG) bcast_g(e1, half*64);
      else bcast_lists(sm, ENo, half*64);
    } else if constexpr (BIG){
      run_mlp_big<2*DE, false, ING, OUTG>(sm, R,
        P.Wc1, P.bc1, P.Wc2, P.bc2, ENo, e1, e1, chkRow);
    } else {
      run_mlp_small<2*DE, false, RTF, ING, OUTG>(sm, R,
        P.Wc1, P.bc1, P.Wc2, P.bc2, ENo, e1, e1, chkRow);
    }

    decode_node<half, LVL+1>(sm, e1, leaf_base, P, f);

    __syncthreads();
    for (int idx = threadIdx.x; idx < R; idx += NT){
      sm.U1[SK+idx]  = sm.Uout[ON+idx];
      sm.X1[SK+idx]  = sm.Xout[ON+idx];
      sm.L1f[SK+idx] = sm.Lout[ON+idx];
    }
    if (threadIdx.x < 8) sm.Ord1[LVL*8 + threadIdx.x] = sm.Ret[threadIdx.x];
    __syncthreads();

    auto bitRow = [&](int r)->RowOff {
      int l = r / half, t = r - l*half;
      int ol = sm.Ord1[LVL*8 + l];
      int e;
      if constexpr (L0)            e = EO0 + 2*t*64;
      else if constexpr (ING)      e = (ol*NK + 2*t)*64;
      else                         e = EKo + (ol*NK + 2*t)*64;
      int bit = sm.X1[SK + l*half + t];
      return {e, bit};
    };
    const bool ub = (sm.first_info >= leaf_base + half);
    if (ub){
      run_mlp_small<2*DE, true, RTU, ING, OUTG>(sm, half,
        P.Wb1, P.bb1, P.Wb2, P.bb2, ENo, e1, e1, bitRow);
      if constexpr (OUTG) bcast_g(e1, half*64);
      else bcast_lists(sm, ENo, half*64);
    } else if constexpr (BIG){
      run_mlp_big<2*DE, true, ING, OUTG>(sm, R,
        P.Wb1, P.bb1, P.Wb2, P.bb2, ENo, e1, e1, bitRow);
    } else {
      run_mlp_small<2*DE, true, RTF, ING, OUTG>(sm, R,
        P.Wb1, P.bb1, P.Wb2, P.bb2, ENo, e1, e1, bitRow);
    }

    decode_node<half, LVL+1>(sm, e1, leaf_base + half, P, f);

    __syncthreads();
    if (threadIdx.x < 8) sm.Ord2[threadIdx.x] = sm.Ret[threadIdx.x];
    __syncthreads();
    for (int idx = threadIdx.x; idx < R; idx += NT){
      int l = idx / half, t = idx - l*half;
      int o2 = sm.Ord2[l];
      int   u1 = sm.U1[SK + o2*half + t];
      int   x1 = sm.X1[SK + o2*half + t];
      float l1 = sm.L1f[SK + o2*half + t];
      int   u2 = sm.Uout[ON + idx];
      int   x2 = sm.Xout[ON + idx];
      float l2 = sm.Lout[ON + idx];
      sm.Uout[OK + l*NK + t]        = u1;
      sm.Uout[OK + l*NK + half + t] = u2;
      sm.Lout[OK + l*NK + t]        = l1;
      sm.Lout[OK + l*NK + half + t] = l2;
      sm.Xout[OK + l*NK + 2*t]      = (x1 + x2) & 1;
      sm.Xout[OK + l*NK + 2*t + 1]  = x2;
    }
    __syncthreads();
    if (threadIdx.x < 8) sm.Ret[threadIdx.x] = sm.Ord1[LVL*8 + sm.Ord2[threadIdx.x]];
    __syncthreads();
  }
}

__global__ void __launch_bounds__(NT, 1)
scl_kernel(Params P, const float* __restrict__ y, const int* __restrict__ f,
           float* __restrict__ out, int out_size)
{
  extern __shared__ char smem_raw[];
  Smem& sm = *reinterpret_cast<Smem*>(smem_raw);
  const int b = blockIdx.x, tid = threadIdx.x;
  float* e1 = g_E1[b];
  if (tid < 8) sm.Pm[tid] = (tid == 0) ? 0.f : 1e8f;
  if (tid == 0){
    int fi = 64;
    for (int i = 0; i < 64; i++) if (f[i] == 2){ fi = i; break; }
    sm.first_info = fi;
  }
  if (tid < 256) sm.EALL[YO + tid] = y[b*256 + tid];    // obs input rows

  // precompute embH[bit][h] = sum_k W_bit1[128+k][h] * emb[bit][k]
  {
    int bit = tid >> 8, h = tid & 255;
    float s = 0.f;
    #pragma unroll
    for (int k = 0; k < DU; k++)
      s = fmaf(P.Wb1[(128+k)*HD + h], P.emb[bit*DU + k], s);
    g_embH[bit*HD + h] = s;
  }
  __syncthreads();

  // observation MLP (K=4) -> E0 (single list, smem)
  run_mlp_big<4, false, false, false>(sm, 64, P.Wo1, P.bo1, P.Wo2, P.bo2, EO0,
    nullptr, nullptr, [&](int r)->RowOff { return {YO + r*4, 0}; });

  decode_node<64, 0>(sm, e1, 0, P, f);

  if (tid == 0){
    int best = 0; float bv = sm.Pm[0];
    for (int l=1;l<8;l++) if (sm.Pm[l] < bv){ bv = sm.Pm[l]; best = l; }
    sm.Ord2[0] = best;
  }
  __syncthreads();
  const int best = sm.Ord2[0];

  if (out_size >= 8192 + 65536){
    for (int t = tid; t < 64; t += NT)
      out[b*64 + t] = (float)sm.Uout[best*64 + t];
    for (int idx = tid; idx < 512; idx += NT)
      out[8192 + b*512 + idx] = sm.Lout[idx];
  } else if (out_size == 8192){
    for (int t = tid; t < 64; t += NT)
      out[b*64 + t] = (float)sm.Uout[best*64 + t];
  } else {
    for (int idx = tid; idx < 512 && (b*512 + idx) < out_size; idx += NT)
      out[b*512 + idx] = sm.Lout[idx];
  }
}

extern "C" void kernel_launch(void* const* d_in, const int* in_sizes, int n_in,
                              void* d_out, int out_size)
{
  Params P;
  const float* y  = (const float*)d_in[0];
  const int*   f  = (const int*)  d_in[1];
  P.Wo1  = (const float*)d_in[2];
  P.bo1  = (const float*)d_in[3];
  P.Wo2  = (const float*)d_in[4];
  P.bo2  = (const float*)d_in[5];
  P.Wc1  = (const float*)d_in[6];
  P.bc1  = (const float*)d_in[7];
  P.Wc2  = (const float*)d_in[8];
  P.bc2  = (const float*)d_in[9];
  P.Wb1  = (const float*)d_in[10];
  P.bb1  = (const float*)d_in[11];
  P.Wb2  = (const float*)d_in[12];
  P.bb2  = (const float*)d_in[13];
  P.Wllr = (const float*)d_in[14];
  P.bllr = (const float*)d_in[15];
  P.emb  = (const float*)d_in[16];

  cudaFuncSetAttribute(scl_kernel, cudaFuncAttributeMaxDynamicSharedMemorySize,
                       (int)sizeof(Smem));
  scl_kernel<<<NB, NT, sizeof(Smem)>>>(P, y, f, (float*)d_out, out_size);
}